// round 6
// baseline (speedup 1.0000x reference)
#include <cuda_runtime.h>

#define Bc 64
#define Tc 2000
#define Lc 400
#define Mc 80
#define EPSc 1e-8f

// accumulators: 0=s1(mel1), 1=s2(mel2), 2=gate, 3=kl_sum, 4=ent_sum(Σ p*logp)
__device__ double g_acc[5];

__device__ __forceinline__ float warp_sum(float v) {
    v += __shfl_xor_sync(0xffffffffu, v, 16);
    v += __shfl_xor_sync(0xffffffffu, v, 8);
    v += __shfl_xor_sync(0xffffffffu, v, 4);
    v += __shfl_xor_sync(0xffffffffu, v, 2);
    v += __shfl_xor_sync(0xffffffffu, v, 1);
    return v;
}

__global__ void init_kernel() {
    if (threadIdx.x < 5) g_acc[threadIdx.x] = 0.0;
}

// ---------------- attn rows: KL + entropy, one warp per (b,t) row ----------
// VERBATIM R1 math (verified at rel_err 9.1e-8):
// kl_row = (A - sg*lnS)/S with A = sum g*(h - logp), S = sg + EPS,
// g = exp(h), h = -0.5*((l-ep)/sigma)^2, for l < Lb.
__device__ __forceinline__ void attn_work(int aid, const float4* __restrict__ attn,
                                          const int* __restrict__ text_len,
                                          float* sred) {
    int lane = threadIdx.x & 31, wid = threadIdx.x >> 5;
    int gwarp = aid * 8 + wid;             // row id in [0, B*T)
    int b = gwarp / Tc;
    int t = gwarp - b * Tc;

    int Lb = __ldg(&text_len[b]);
    float sigma = fminf(fmaxf((float)Lb * 0.05f, 3.0f), 10.0f);
    float inv_sig = 1.0f / sigma;
    int ep_i = (t * Lb) / Tc;
    if (ep_i > Lb - 1) ep_i = Lb - 1;
    float ep = (float)ep_i;

    const float4* row = attn + gwarp * (Lc / 4);

    float sg = 0.f, A = 0.f, E = 0.f;
    for (int j = lane; j < Lc / 4; j += 32) {
        float4 a4 = row[j];
        int l0 = j * 4;
        float av[4] = {a4.x, a4.y, a4.z, a4.w};
#pragma unroll
        for (int k = 0; k < 4; k++) {
            float a = fmaxf(av[k], EPSc);
            float lp = __logf(a);
            E += a * lp;
            int l = l0 + k;
            if (l < Lb) {
                float zz = ((float)l - ep) * inv_sig;
                float h = -0.5f * zz * zz;
                float g = __expf(h);
                sg += g;
                A += g * (h - lp);
            }
        }
    }
    sg = warp_sum(sg);
    A = warp_sum(A);
    E = warp_sum(E);

    if (lane == 0) {
        float S = sg + EPSc;
        float lnS = __logf(S);
        sred[wid]     = (A - sg * lnS) / S;   // kl_row
        sred[8 + wid] = E;                    // Σ a*ln(a)
    }
    __syncthreads();
    if (wid == 0) {
        float kl = (lane < 8) ? sred[lane] : 0.f;
        float en = (lane < 8) ? sred[8 + lane] : 0.f;
        kl = warp_sum(kl);
        en = warp_sum(en);
        if (lane == 0) {
            atomicAdd(&g_acc[3], (double)kl);
            atomicAdd(&g_acc[4], (double)en);
        }
    }
}

// ---------------- mel L1 losses (grid-stride over float4) ------------------
__device__ __forceinline__ void mel_work(int mid, int nmel,
                                         const float4* __restrict__ post,
                                         const float4* __restrict__ out,
                                         const float4* __restrict__ tgt,
                                         const int* __restrict__ mel_len,
                                         float* sred) {
    const int n4 = Bc * Tc * Mc / 4;
    int stride = nmel * blockDim.x;
    float s1 = 0.f, s2 = 0.f;
    for (int i = mid * blockDim.x + threadIdx.x; i < n4; i += stride) {
        int rowi = i / (Mc / 4);
        int b = rowi / Tc;
        int t = rowi - b * Tc;
        if (t < __ldg(&mel_len[b])) {
            float4 o = out[i], p = post[i], g = tgt[i];
            s1 += (fabsf(o.x - g.x) + fabsf(o.y - g.y)) + (fabsf(o.z - g.z) + fabsf(o.w - g.w));
            s2 += (fabsf(p.x - g.x) + fabsf(p.y - g.y)) + (fabsf(p.z - g.z) + fabsf(p.w - g.w));
        }
    }
    int lane = threadIdx.x & 31, wid = threadIdx.x >> 5;
    s1 = warp_sum(s1);
    s2 = warp_sum(s2);
    if (lane == 0) { sred[wid] = s1; sred[8 + wid] = s2; }
    __syncthreads();
    if (wid == 0) {
        float a = (lane < 8) ? sred[lane] : 0.f;
        float c = (lane < 8) ? sred[8 + lane] : 0.f;
        a = warp_sum(a);
        c = warp_sum(c);
        if (lane == 0) {
            atomicAdd(&g_acc[0], (double)a);
            atomicAdd(&g_acc[1], (double)c);
        }
    }
}

// ---------------- gate BCE-with-logits -------------------------------------
__device__ __forceinline__ void gate_work(int gid, int ngate,
                                          const float* __restrict__ x,
                                          const float* __restrict__ z,
                                          float* sred) {
    const int n = Bc * Tc;
    int stride = ngate * blockDim.x;
    float s = 0.f;
    for (int i = gid * blockDim.x + threadIdx.x; i < n; i += stride) {
        float xi = x[i], zi = z[i];
        s += fmaxf(xi, 0.f) - xi * zi + log1pf(__expf(-fabsf(xi)));
    }
    int lane = threadIdx.x & 31, wid = threadIdx.x >> 5;
    s = warp_sum(s);
    if (lane == 0) sred[wid] = s;
    __syncthreads();
    if (wid == 0) {
        float a = (lane < 8) ? sred[lane] : 0.f;
        a = warp_sum(a);
        if (lane == 0) atomicAdd(&g_acc[2], (double)a);
    }
}

// ---------------- fused kernel: block specialization -----------------------
// bid < 17000: r = bid%17; r==16 -> mel block q (q=bid/17, 1000 mel blocks)
//              r<16     -> attn id = q*16+r    (16000 attn ids x 8 rows = 128000 rows)
// bid >= 17000: gate block (6 blocks)
#define N_MEL 1000
#define N_GATE 6
#define GRID_TOTAL (17 * N_MEL + N_GATE)

__global__ void __launch_bounds__(256)
fused_kernel(const float4* __restrict__ post,
             const float4* __restrict__ out,
             const float*  __restrict__ gate_x,
             const float4* __restrict__ attn,
             const float4* __restrict__ tgt,
             const float*  __restrict__ gate_z,
             const int* __restrict__ mel_len,
             const int* __restrict__ text_len) {
    __shared__ float sred[16];
    int bid = blockIdx.x;
    if (bid >= 17 * N_MEL) {
        gate_work(bid - 17 * N_MEL, N_GATE, gate_x, gate_z, sred);
        return;
    }
    int q = bid / 17;
    int r = bid - 17 * q;
    if (r == 16) {
        mel_work(q, N_MEL, post, out, tgt, mel_len, sred);
    } else {
        attn_work(q * 16 + r, attn, text_len, sred);
    }
}

// ---------------- finalize ----------------
__global__ void final_kernel(const int* __restrict__ mel_len,
                             float* __restrict__ outp) {
    if (threadIdx.x == 0 && blockIdx.x == 0) {
        double nvalid = 0.0;
        for (int b = 0; b < Bc; b++) nvalid += (double)mel_len[b];
        nvalid *= (double)Mc;

        double loss_mel = (g_acc[0] + g_acc[1]) / nvalid;
        double loss_gate = g_acc[2] / (double)(Bc * Tc);
        double kl = g_acc[3] / (double)Bc / (double)Tc;
        if (kl > 150.0) kl = 150.0;
        double ent = -g_acc[4] / (double)(Bc * Tc);
        double ratio = ent / 3.5;
        if (ratio < 0.0) ratio = 0.0;
        double w;
        if (ent <= 3.5) {
            w = ratio > 0.2 ? ratio : 0.2;
        } else {
            w = 1.0;
        }
        double total = loss_mel + loss_gate + w * kl;
        outp[0] = (float)total;
        outp[1] = (float)loss_mel;
        outp[2] = (float)loss_gate;
        outp[3] = (float)kl;
    }
}

extern "C" void kernel_launch(void* const* d_in, const int* in_sizes, int n_in,
                              void* d_out, int out_size) {
    const float* mel_out_postnet = (const float*)d_in[0];
    const float* mel_out         = (const float*)d_in[1];
    const float* gate_out        = (const float*)d_in[2];
    const float* alignments      = (const float*)d_in[3];
    const float* mel_target      = (const float*)d_in[4];
    const float* gate_target     = (const float*)d_in[5];
    const int*   mel_lengths     = (const int*)d_in[6];
    const int*   text_lengths    = (const int*)d_in[7];
    float* outp = (float*)d_out;

    init_kernel<<<1, 32>>>();
    fused_kernel<<<GRID_TOTAL, 256>>>((const float4*)mel_out_postnet,
                                      (const float4*)mel_out,
                                      gate_out,
                                      (const float4*)alignments,
                                      (const float4*)mel_target,
                                      gate_target,
                                      mel_lengths, text_lengths);
    final_kernel<<<1, 32>>>(mel_lengths, outp);
    (void)in_sizes; (void)n_in; (void)out_size;
}

// round 7
// speedup vs baseline: 1.0886x; 1.0886x over previous
#include <cuda_runtime.h>

#define Bc 64
#define Tc 2000
#define Lc 400
#define Mc 80
#define EPSc 1e-8f

// accumulators: 0=s1(mel1), 1=s2(mel2), 2=gate, 3=kl_sum, 4=ent_sum(Σ p*logp)
// Zero-initialized at module load; final_kernel re-zeros after each use so
// every kernel_launch (and every graph replay) starts from zero.
__device__ double g_acc[5];

__device__ __forceinline__ float warp_sum(float v) {
    v += __shfl_xor_sync(0xffffffffu, v, 16);
    v += __shfl_xor_sync(0xffffffffu, v, 8);
    v += __shfl_xor_sync(0xffffffffu, v, 4);
    v += __shfl_xor_sync(0xffffffffu, v, 2);
    v += __shfl_xor_sync(0xffffffffu, v, 1);
    return v;
}

// ---------------- mel L1 losses ----------------
__global__ void mel_kernel(const float4* __restrict__ post,
                           const float4* __restrict__ out,
                           const float4* __restrict__ tgt,
                           const int* __restrict__ mel_len) {
    const int n4 = Bc * Tc * Mc / 4;  // 2,048,000
    float s1 = 0.f, s2 = 0.f;
    for (int i = blockIdx.x * blockDim.x + threadIdx.x; i < n4;
         i += gridDim.x * blockDim.x) {
        int row = i / (Mc / 4);
        int b = row / Tc;
        int t = row - b * Tc;
        if (t < __ldg(&mel_len[b])) {
            float4 o = out[i], p = post[i], g = tgt[i];
            s1 += (fabsf(o.x - g.x) + fabsf(o.y - g.y)) + (fabsf(o.z - g.z) + fabsf(o.w - g.w));
            s2 += (fabsf(p.x - g.x) + fabsf(p.y - g.y)) + (fabsf(p.z - g.z) + fabsf(p.w - g.w));
        }
    }
    __shared__ float sm1[8], sm2[8];
    int lane = threadIdx.x & 31, wid = threadIdx.x >> 5;
    s1 = warp_sum(s1);
    s2 = warp_sum(s2);
    if (lane == 0) { sm1[wid] = s1; sm2[wid] = s2; }
    __syncthreads();
    if (wid == 0) {
        float a = (lane < 8) ? sm1[lane] : 0.f;
        float b2 = (lane < 8) ? sm2[lane] : 0.f;
        a = warp_sum(a);
        b2 = warp_sum(b2);
        if (lane == 0) {
            atomicAdd(&g_acc[0], (double)a);
            atomicAdd(&g_acc[1], (double)b2);
        }
    }
}

// ---------------- attn (one warp per (b,t) row) + gate in tail blocks ------
// Pass 1: entropy over all 400 columns.
// Pass 2: Gaussian/KL over the compact window l in [ep-67, ep+67] (float4-
//         aligned, clamped to [0, L)), re-loading from L1. R1-verbatim math:
//         h = -0.5*((l-ep)/sigma)^2, g = __expf(h), A += g*(h - __logf(a)),
//         exact integer mask l < Lb. Outside-window g < 4e-10 (truncated).
#define ATTN_BLOCKS 16000
#define GATE_BLOCKS 64

__global__ void __launch_bounds__(256)
attn_gate_kernel(const float4* __restrict__ attn,
                 const int* __restrict__ text_len,
                 const float* __restrict__ gate_x,
                 const float* __restrict__ gate_z) {
    __shared__ float sred[16];
    int lane = threadIdx.x & 31, wid = threadIdx.x >> 5;

    if (blockIdx.x >= ATTN_BLOCKS) {
        // ---- gate BCE-with-logits ----
        int gid = blockIdx.x - ATTN_BLOCKS;
        const int n = Bc * Tc;
        int stride = GATE_BLOCKS * blockDim.x;
        float s = 0.f;
        for (int i = gid * blockDim.x + threadIdx.x; i < n; i += stride) {
            float xi = gate_x[i], zi = gate_z[i];
            s += fmaxf(xi, 0.f) - xi * zi + log1pf(__expf(-fabsf(xi)));
        }
        s = warp_sum(s);
        if (lane == 0) sred[wid] = s;
        __syncthreads();
        if (wid == 0) {
            float a = (lane < 8) ? sred[lane] : 0.f;
            a = warp_sum(a);
            if (lane == 0) atomicAdd(&g_acc[2], (double)a);
        }
        return;
    }

    int gwarp = blockIdx.x * 8 + wid;   // row id in [0, B*T)
    int b = gwarp / Tc;
    int t = gwarp - b * Tc;

    int Lb = __ldg(&text_len[b]);
    float sigma = fminf(fmaxf((float)Lb * 0.05f, 3.0f), 10.0f);
    float inv_sig = 1.0f / sigma;
    int ep_i = (t * Lb) / Tc;
    if (ep_i > Lb - 1) ep_i = Lb - 1;
    float ep = (float)ep_i;

    const float4* row = attn + gwarp * (Lc / 4);

    // ---- pass 1: entropy over all columns ----
    float E = 0.f;
    for (int j = lane; j < Lc / 4; j += 32) {
        float4 a4 = row[j];
        float a0 = fmaxf(a4.x, EPSc);
        float a1 = fmaxf(a4.y, EPSc);
        float a2 = fmaxf(a4.z, EPSc);
        float a3 = fmaxf(a4.w, EPSc);
        E += a0 * __logf(a0);
        E += a1 * __logf(a1);
        E += a2 * __logf(a2);
        E += a3 * __logf(a3);
    }

    // ---- pass 2: Gaussian/KL over compact window (<= 2 iterations) ----
    int j4lo = ep_i > 67 ? (ep_i - 67) >> 2 : 0;
    int j4hi_full = (ep_i + 67) >> 2;
    int j4hi = j4hi_full < (Lc / 4 - 1) ? j4hi_full : (Lc / 4 - 1);

    float sg = 0.f, A = 0.f;
    for (int jj = j4lo + lane; jj <= j4hi; jj += 32) {
        float4 a4 = row[jj];
        int l0 = jj * 4;
        float av[4] = {a4.x, a4.y, a4.z, a4.w};
#pragma unroll
        for (int k = 0; k < 4; k++) {
            int l = l0 + k;
            if (l < Lb) {
                float a = fmaxf(av[k], EPSc);
                float lp = __logf(a);
                float zz = ((float)l - ep) * inv_sig;
                float h = -0.5f * zz * zz;
                float g = __expf(h);
                sg += g;
                A += g * (h - lp);
            }
        }
    }

    sg = warp_sum(sg);
    A = warp_sum(A);
    E = warp_sum(E);

    if (lane == 0) {
        float S = sg + EPSc;
        float lnS = __logf(S);
        sred[wid]     = (A - sg * lnS) / S;   // kl_row
        sred[8 + wid] = E;                    // Σ a*ln(a)
    }
    __syncthreads();
    if (wid == 0) {
        float kl = (lane < 8) ? sred[lane] : 0.f;
        float en = (lane < 8) ? sred[8 + lane] : 0.f;
        kl = warp_sum(kl);
        en = warp_sum(en);
        if (lane == 0) {
            atomicAdd(&g_acc[3], (double)kl);
            atomicAdd(&g_acc[4], (double)en);
        }
    }
}

// ---------------- finalize (and re-zero accumulators) ----------------
__global__ void final_kernel(const int* __restrict__ mel_len,
                             float* __restrict__ outp) {
    if (threadIdx.x == 0 && blockIdx.x == 0) {
        double nvalid = 0.0;
        for (int b = 0; b < Bc; b++) nvalid += (double)mel_len[b];
        nvalid *= (double)Mc;

        double loss_mel = (g_acc[0] + g_acc[1]) / nvalid;
        double loss_gate = g_acc[2] / (double)(Bc * Tc);
        double kl = g_acc[3] / (double)Bc / (double)Tc;
        if (kl > 150.0) kl = 150.0;
        double ent = -g_acc[4] / (double)(Bc * Tc);
        double ratio = ent / 3.5;
        if (ratio < 0.0) ratio = 0.0;
        double w;
        if (ent <= 3.5) {
            w = ratio > 0.2 ? ratio : 0.2;
        } else {
            w = 1.0;
        }
        double total = loss_mel + loss_gate + w * kl;
        outp[0] = (float)total;
        outp[1] = (float)loss_mel;
        outp[2] = (float)loss_gate;
        outp[3] = (float)kl;

        // reset for the next (replayed) invocation
        g_acc[0] = 0.0; g_acc[1] = 0.0; g_acc[2] = 0.0;
        g_acc[3] = 0.0; g_acc[4] = 0.0;
    }
}

extern "C" void kernel_launch(void* const* d_in, const int* in_sizes, int n_in,
                              void* d_out, int out_size) {
    const float* mel_out_postnet = (const float*)d_in[0];
    const float* mel_out         = (const float*)d_in[1];
    const float* gate_out        = (const float*)d_in[2];
    const float* alignments      = (const float*)d_in[3];
    const float* mel_target      = (const float*)d_in[4];
    const float* gate_target     = (const float*)d_in[5];
    const int*   mel_lengths     = (const int*)d_in[6];
    const int*   text_lengths    = (const int*)d_in[7];
    float* outp = (float*)d_out;

    mel_kernel<<<2368, 256>>>((const float4*)mel_out_postnet,
                              (const float4*)mel_out,
                              (const float4*)mel_target, mel_lengths);
    attn_gate_kernel<<<ATTN_BLOCKS + GATE_BLOCKS, 256>>>(
        (const float4*)alignments, text_lengths, gate_out, gate_target);
    final_kernel<<<1, 32>>>(mel_lengths, outp);
    (void)in_sizes; (void)n_in; (void)out_size;
}

// round 8
// speedup vs baseline: 1.1640x; 1.0692x over previous
#include <cuda_runtime.h>

#define Bc 64
#define Tc 2000
#define Lc 400
#define Mc 80
#define EPSc 1e-8f
#define LN2f 0.69314718055994531f
// sqrt(0.5 / ln 2) = sqrt(0.5 * log2(e)) — so that 2^{-(z*K)^2} = e^{-z^2/2}
#define SQHL2E 0.84932180028801905f

// accumulators: 0=s1(mel1), 1=s2(mel2), 2=gate, 3=kl_sum, 4=ent_sum(Σ p*logp)
// Zero at module load; final_kernel re-zeros after use (graph-replay safe).
__device__ double g_acc[5];

__device__ __forceinline__ float warp_sum(float v) {
    v += __shfl_xor_sync(0xffffffffu, v, 16);
    v += __shfl_xor_sync(0xffffffffu, v, 8);
    v += __shfl_xor_sync(0xffffffffu, v, 4);
    v += __shfl_xor_sync(0xffffffffu, v, 2);
    v += __shfl_xor_sync(0xffffffffu, v, 1);
    return v;
}

// ---------------- mel L1 losses (2x unrolled grid-stride) ------------------
__global__ void __launch_bounds__(256)
mel_kernel(const float4* __restrict__ post,
           const float4* __restrict__ out,
           const float4* __restrict__ tgt,
           const int* __restrict__ mel_len) {
    const int n4 = Bc * Tc * Mc / 4;  // 2,048,000
    float s1 = 0.f, s2 = 0.f;
    int stride = gridDim.x * blockDim.x;
    for (int i = blockIdx.x * blockDim.x + threadIdx.x; i < n4; i += 2 * stride) {
        int i2 = i + stride;
        int row0 = i / (Mc / 4);
        int b0 = row0 / Tc;
        int t0 = row0 - b0 * Tc;
        bool v0 = t0 < __ldg(&mel_len[b0]);
        bool v1 = false;
        int b1 = 0, t1 = 0;
        if (i2 < n4) {
            int row1 = i2 / (Mc / 4);
            b1 = row1 / Tc;
            t1 = row1 - b1 * Tc;
            v1 = t1 < __ldg(&mel_len[b1]);
        }
        if (v0) {
            float4 o = out[i], p = post[i], g = tgt[i];
            s1 += (fabsf(o.x - g.x) + fabsf(o.y - g.y)) + (fabsf(o.z - g.z) + fabsf(o.w - g.w));
            s2 += (fabsf(p.x - g.x) + fabsf(p.y - g.y)) + (fabsf(p.z - g.z) + fabsf(p.w - g.w));
        }
        if (v1) {
            float4 o = out[i2], p = post[i2], g = tgt[i2];
            s1 += (fabsf(o.x - g.x) + fabsf(o.y - g.y)) + (fabsf(o.z - g.z) + fabsf(o.w - g.w));
            s2 += (fabsf(p.x - g.x) + fabsf(p.y - g.y)) + (fabsf(p.z - g.z) + fabsf(p.w - g.w));
        }
    }
    __shared__ float sm1[8], sm2[8];
    int lane = threadIdx.x & 31, wid = threadIdx.x >> 5;
    s1 = warp_sum(s1);
    s2 = warp_sum(s2);
    if (lane == 0) { sm1[wid] = s1; sm2[wid] = s2; }
    __syncthreads();
    if (wid == 0) {
        float a = (lane < 8) ? sm1[lane] : 0.f;
        float b2 = (lane < 8) ? sm2[lane] : 0.f;
        a = warp_sum(a);
        b2 = warp_sum(b2);
        if (lane == 0) {
            atomicAdd(&g_acc[0], (double)a);
            atomicAdd(&g_acc[1], (double)b2);
        }
    }
}

// ---------------- attn (one warp per (b,t) row) + gate in tail blocks ------
// Pass 1 (all 400 cols, log2 domain): E2 += a * log2(a);  E = ln2*E2.
// Pass 2 (window l in [ep-67, ep+67], log2 domain, CORRECT constant):
//   u = (l-ep)*K2, K2 = sqrt(.5*log2e)/sigma; h2 = -u*u; g = 2^h2 = e^{-z^2/2}
//   A2 += g*(h2 - log2(a)) for l < Lb;  A = ln2*A2.
//   kl_row = (ln2*A2 - sg*ln(S))/S, S = sg + EPS.
#define ATTN_BLOCKS 16000
#define GATE_BLOCKS 64

__global__ void __launch_bounds__(256)
attn_gate_kernel(const float4* __restrict__ attn,
                 const int* __restrict__ text_len,
                 const float* __restrict__ gate_x,
                 const float* __restrict__ gate_z) {
    __shared__ float sred[16];
    int lane = threadIdx.x & 31, wid = threadIdx.x >> 5;

    if (blockIdx.x >= ATTN_BLOCKS) {
        // ---- gate BCE-with-logits ----
        int gid = blockIdx.x - ATTN_BLOCKS;
        const int n = Bc * Tc;
        int stride = GATE_BLOCKS * blockDim.x;
        float s = 0.f;
        for (int i = gid * blockDim.x + threadIdx.x; i < n; i += stride) {
            float xi = gate_x[i], zi = gate_z[i];
            s += fmaxf(xi, 0.f) - xi * zi + log1pf(__expf(-fabsf(xi)));
        }
        s = warp_sum(s);
        if (lane == 0) sred[wid] = s;
        __syncthreads();
        if (wid == 0) {
            float a = (lane < 8) ? sred[lane] : 0.f;
            a = warp_sum(a);
            if (lane == 0) atomicAdd(&g_acc[2], (double)a);
        }
        return;
    }

    int gwarp = blockIdx.x * 8 + wid;   // row id in [0, B*T)
    int b = gwarp / Tc;
    int t = gwarp - b * Tc;

    int Lb = __ldg(&text_len[b]);
    float sigma = fminf(fmaxf((float)Lb * 0.05f, 3.0f), 10.0f);
    int ep_i = (t * Lb) / Tc;
    if (ep_i > Lb - 1) ep_i = Lb - 1;
    float ep = (float)ep_i;
    float K2 = SQHL2E / sigma;

    const float4* row = attn + gwarp * (Lc / 4);

    // ---- pass 1: entropy over all 400 columns (log2 domain, unrolled) ----
    float E2 = 0.f;
#pragma unroll
    for (int it = 0; it < 4; it++) {
        int j = lane + it * 32;
        if (it < 3 || lane < 4) {      // j < 100
            float4 a4 = row[j];
            float a0 = fmaxf(a4.x, EPSc);
            float a1 = fmaxf(a4.y, EPSc);
            float a2 = fmaxf(a4.z, EPSc);
            float a3 = fmaxf(a4.w, EPSc);
            E2 += a0 * __log2f(a0);
            E2 += a1 * __log2f(a1);
            E2 += a2 * __log2f(a2);
            E2 += a3 * __log2f(a3);
        }
    }

    // ---- pass 2: Gaussian/KL over compact window (L1-resident reload) ----
    int j4lo = ep_i > 67 ? (ep_i - 67) >> 2 : 0;
    int j4hi_full = (ep_i + 67) >> 2;
    int j4hi = j4hi_full < (Lc / 4 - 1) ? j4hi_full : (Lc / 4 - 1);

    float sg = 0.f, A2 = 0.f;
    float K2x2 = K2 + K2;
    for (int jj = j4lo + lane; jj <= j4hi; jj += 32) {
        float4 a4 = row[jj];
        int l0 = jj * 4;
        float u0 = ((float)l0 - ep) * K2;
        float u1 = u0 + K2;
        float u2 = u0 + K2x2;
        float u3 = u2 + K2;
        float p0 = __log2f(fmaxf(a4.x, EPSc));
        float p1 = __log2f(fmaxf(a4.y, EPSc));
        float p2 = __log2f(fmaxf(a4.z, EPSc));
        float p3 = __log2f(fmaxf(a4.w, EPSc));
        float h0 = -u0 * u0;
        float h1 = -u1 * u1;
        float h2 = -u2 * u2;
        float h3 = -u3 * u3;
        float g0 = (l0 + 0 < Lb) ? exp2f(h0) : 0.f;
        float g1 = (l0 + 1 < Lb) ? exp2f(h1) : 0.f;
        float g2 = (l0 + 2 < Lb) ? exp2f(h2) : 0.f;
        float g3 = (l0 + 3 < Lb) ? exp2f(h3) : 0.f;
        sg += (g0 + g1) + (g2 + g3);
        A2 += g0 * (h0 - p0);
        A2 += g1 * (h1 - p1);
        A2 += g2 * (h2 - p2);
        A2 += g3 * (h3 - p3);
    }

    sg = warp_sum(sg);
    A2 = warp_sum(A2);
    E2 = warp_sum(E2);

    if (lane == 0) {
        float S = sg + EPSc;
        float lnS = __logf(S);
        sred[wid]     = (LN2f * A2 - sg * lnS) / S;   // kl_row (natural log)
        sred[8 + wid] = LN2f * E2;                    // Σ a*ln(a)
    }
    __syncthreads();
    if (wid == 0) {
        float kl = (lane < 8) ? sred[lane] : 0.f;
        float en = (lane < 8) ? sred[8 + lane] : 0.f;
        kl = warp_sum(kl);
        en = warp_sum(en);
        if (lane == 0) {
            atomicAdd(&g_acc[3], (double)kl);
            atomicAdd(&g_acc[4], (double)en);
        }
    }
}

// ---------------- finalize (and re-zero accumulators) ----------------
__global__ void final_kernel(const int* __restrict__ mel_len,
                             float* __restrict__ outp) {
    if (threadIdx.x == 0 && blockIdx.x == 0) {
        double nvalid = 0.0;
        for (int b = 0; b < Bc; b++) nvalid += (double)mel_len[b];
        nvalid *= (double)Mc;

        double loss_mel = (g_acc[0] + g_acc[1]) / nvalid;
        double loss_gate = g_acc[2] / (double)(Bc * Tc);
        double kl = g_acc[3] / (double)Bc / (double)Tc;
        if (kl > 150.0) kl = 150.0;
        double ent = -g_acc[4] / (double)(Bc * Tc);
        double ratio = ent / 3.5;
        if (ratio < 0.0) ratio = 0.0;
        double w;
        if (ent <= 3.5) {
            w = ratio > 0.2 ? ratio : 0.2;
        } else {
            w = 1.0;
        }
        double total = loss_mel + loss_gate + w * kl;
        outp[0] = (float)total;
        outp[1] = (float)loss_mel;
        outp[2] = (float)loss_gate;
        outp[3] = (float)kl;

        // reset for the next (replayed) invocation
        g_acc[0] = 0.0; g_acc[1] = 0.0; g_acc[2] = 0.0;
        g_acc[3] = 0.0; g_acc[4] = 0.0;
    }
}

extern "C" void kernel_launch(void* const* d_in, const int* in_sizes, int n_in,
                              void* d_out, int out_size) {
    const float* mel_out_postnet = (const float*)d_in[0];
    const float* mel_out         = (const float*)d_in[1];
    const float* gate_out        = (const float*)d_in[2];
    const float* alignments      = (const float*)d_in[3];
    const float* mel_target      = (const float*)d_in[4];
    const float* gate_target     = (const float*)d_in[5];
    const int*   mel_lengths     = (const int*)d_in[6];
    const int*   text_lengths    = (const int*)d_in[7];
    float* outp = (float*)d_out;

    mel_kernel<<<2368, 256>>>((const float4*)mel_out_postnet,
                              (const float4*)mel_out,
                              (const float4*)mel_target, mel_lengths);
    attn_gate_kernel<<<ATTN_BLOCKS + GATE_BLOCKS, 256>>>(
        (const float4*)alignments, text_lengths, gate_out, gate_target);
    final_kernel<<<1, 32>>>(mel_lengths, outp);
    (void)in_sizes; (void)n_in; (void)out_size;
}

// round 9
// speedup vs baseline: 1.3308x; 1.1433x over previous
#include <cuda_runtime.h>

#define Bc 64
#define Tc 2000
#define Lc 400
#define Mc 80
#define EPSc 1e-8f
#define LN2f 0.69314718055994531f
// sqrt(0.5 * log2(e)) — so that 2^{-((l-ep)*K2)^2} = e^{-z^2/2}, K2=SQHL2E/sigma
#define SQHL2E 0.84932180028801905f

// accumulators: 0=s1(mel1), 1=s2(mel2), 2=gate, 3=kl_sum, 4=ent_sum(Σ p*logp)
// Zero at module load; final_kernel re-zeros after use (graph-replay safe).
__device__ double g_acc[5];

__device__ __forceinline__ float fast_lg2(float x) {
    float r;
    asm("lg2.approx.f32 %0, %1;" : "=f"(r) : "f"(x));
    return r;
}
__device__ __forceinline__ float fast_ex2(float x) {
    float r;
    asm("ex2.approx.f32 %0, %1;" : "=f"(r) : "f"(x));
    return r;
}

__device__ __forceinline__ float warp_sum(float v) {
    v += __shfl_xor_sync(0xffffffffu, v, 16);
    v += __shfl_xor_sync(0xffffffffu, v, 8);
    v += __shfl_xor_sync(0xffffffffu, v, 4);
    v += __shfl_xor_sync(0xffffffffu, v, 2);
    v += __shfl_xor_sync(0xffffffffu, v, 1);
    return v;
}

// ---------------- mel L1 losses (2x unrolled grid-stride) ------------------
__global__ void __launch_bounds__(256)
mel_kernel(const float4* __restrict__ post,
           const float4* __restrict__ out,
           const float4* __restrict__ tgt,
           const int* __restrict__ mel_len) {
    const int n4 = Bc * Tc * Mc / 4;  // 2,048,000
    float s1 = 0.f, s2 = 0.f;
    int stride = gridDim.x * blockDim.x;
    for (int i = blockIdx.x * blockDim.x + threadIdx.x; i < n4; i += 2 * stride) {
        int i2 = i + stride;
        int row0 = i / (Mc / 4);
        int b0 = row0 / Tc;
        int t0 = row0 - b0 * Tc;
        bool v0 = t0 < __ldg(&mel_len[b0]);
        bool v1 = false;
        if (i2 < n4) {
            int row1 = i2 / (Mc / 4);
            int b1 = row1 / Tc;
            int t1 = row1 - b1 * Tc;
            v1 = t1 < __ldg(&mel_len[b1]);
        }
        if (v0) {
            float4 o = out[i], p = post[i], g = tgt[i];
            s1 += (fabsf(o.x - g.x) + fabsf(o.y - g.y)) + (fabsf(o.z - g.z) + fabsf(o.w - g.w));
            s2 += (fabsf(p.x - g.x) + fabsf(p.y - g.y)) + (fabsf(p.z - g.z) + fabsf(p.w - g.w));
        }
        if (v1) {
            float4 o = out[i2], p = post[i2], g = tgt[i2];
            s1 += (fabsf(o.x - g.x) + fabsf(o.y - g.y)) + (fabsf(o.z - g.z) + fabsf(o.w - g.w));
            s2 += (fabsf(p.x - g.x) + fabsf(p.y - g.y)) + (fabsf(p.z - g.z) + fabsf(p.w - g.w));
        }
    }
    __shared__ float sm1[8], sm2[8];
    int lane = threadIdx.x & 31, wid = threadIdx.x >> 5;
    s1 = warp_sum(s1);
    s2 = warp_sum(s2);
    if (lane == 0) { sm1[wid] = s1; sm2[wid] = s2; }
    __syncthreads();
    if (wid == 0) {
        float a = (lane < 8) ? sm1[lane] : 0.f;
        float b2 = (lane < 8) ? sm2[lane] : 0.f;
        a = warp_sum(a);
        b2 = warp_sum(b2);
        if (lane == 0) {
            atomicAdd(&g_acc[0], (double)a);
            atomicAdd(&g_acc[1], (double)b2);
        }
    }
}

// ---------------- attn (one warp per (b,t) row) + gate in tail blocks ------
// Single fused loop over 100 float4 chunks (4 warp-iterations):
//   entropy (all elems):  E2 += a * lg2(a)          [FMNMX + MUFU.LG2 + FFMA]
//   Gaussian (in-band its only, warp-uniform test):
//     u = (l-ep)*K2 (affine chain), h2 = -u*u, g = ex2(h2) = e^{-z^2/2},
//     exact mask l < Lb;  sg += g;  A2 += g*(h2 - lg2(a))
//   kl_row = (ln2*A2 - sg*lnS)/S, S = sg+EPS;  ent_row = ln2*E2.
// Out-of-band truncation: g < 4e-10 for |l-ep| > 67 (sigma <= 10).
#define ATTN_BLOCKS 16000
#define GATE_BLOCKS 64

__global__ void __launch_bounds__(256)
attn_gate_kernel(const float4* __restrict__ attn,
                 const int* __restrict__ text_len,
                 const float* __restrict__ gate_x,
                 const float* __restrict__ gate_z) {
    __shared__ float sred[16];
    int lane = threadIdx.x & 31, wid = threadIdx.x >> 5;

    if (blockIdx.x >= ATTN_BLOCKS) {
        // ---- gate BCE-with-logits ----
        int gid = blockIdx.x - ATTN_BLOCKS;
        const int n = Bc * Tc;
        int stride = GATE_BLOCKS * blockDim.x;
        float s = 0.f;
        for (int i = gid * blockDim.x + threadIdx.x; i < n; i += stride) {
            float xi = gate_x[i], zi = gate_z[i];
            s += fmaxf(xi, 0.f) - xi * zi + log1pf(__expf(-fabsf(xi)));
        }
        s = warp_sum(s);
        if (lane == 0) sred[wid] = s;
        __syncthreads();
        if (wid == 0) {
            float a = (lane < 8) ? sred[lane] : 0.f;
            a = warp_sum(a);
            if (lane == 0) atomicAdd(&g_acc[2], (double)a);
        }
        return;
    }

    int gwarp = blockIdx.x * 8 + wid;           // row id in [0, B*T)
    unsigned ub = (unsigned)gwarp / (unsigned)Tc;  // reciprocal-mul division
    int b = (int)ub;
    int t = gwarp - b * Tc;

    int Lb = __ldg(&text_len[b]);
    float sigma = fminf(fmaxf((float)Lb * 0.05f, 3.0f), 10.0f);
    int ep_i = (t * Lb) / Tc;
    if (ep_i > Lb - 1) ep_i = Lb - 1;
    float ep = (float)ep_i;
    float K2 = SQHL2E / sigma;
    int band_lo = ep_i - 67, band_hi = ep_i + 67;

    const float4* row = attn + gwarp * (Lc / 4);
    float lane4K2 = (float)(lane << 2) * K2;

    float E2 = 0.f, sg = 0.f, A2 = 0.f;
#pragma unroll
    for (int it = 0; it < 4; it++) {
        int j = lane + it * 32;
        bool active = (it < 3) || (lane < 4);   // j < 100
        if (active) {
            float4 a4 = row[j];
            float a0 = fmaxf(a4.x, EPSc);
            float a1 = fmaxf(a4.y, EPSc);
            float a2 = fmaxf(a4.z, EPSc);
            float a3 = fmaxf(a4.w, EPSc);
            float p0 = fast_lg2(a0);
            float p1 = fast_lg2(a1);
            float p2 = fast_lg2(a2);
            float p3 = fast_lg2(a3);
            E2 += a0 * p0;
            E2 += a1 * p1;
            E2 += a2 * p2;
            E2 += a3 * p3;

            int l_first = it * 128;
            // warp-uniform band test: iteration's l-range overlaps [band_lo, band_hi]
            if (l_first <= band_hi && l_first + 127 >= band_lo) {
                int lbase = l_first + (lane << 2);
                float u0 = fmaf((float)l_first - ep, K2, lane4K2);
                float u1 = u0 + K2;
                float u2 = u1 + K2;
                float u3 = u2 + K2;
                float h0 = -u0 * u0;
                float h1 = -u1 * u1;
                float h2 = -u2 * u2;
                float h3 = -u3 * u3;
                float g0 = (lbase + 0 < Lb) ? fast_ex2(h0) : 0.f;
                float g1 = (lbase + 1 < Lb) ? fast_ex2(h1) : 0.f;
                float g2 = (lbase + 2 < Lb) ? fast_ex2(h2) : 0.f;
                float g3 = (lbase + 3 < Lb) ? fast_ex2(h3) : 0.f;
                sg += (g0 + g1) + (g2 + g3);
                A2 += g0 * (h0 - p0);
                A2 += g1 * (h1 - p1);
                A2 += g2 * (h2 - p2);
                A2 += g3 * (h3 - p3);
            }
        }
    }

    sg = warp_sum(sg);
    A2 = warp_sum(A2);
    E2 = warp_sum(E2);

    if (lane == 0) {
        float S = sg + EPSc;
        float lnS = LN2f * fast_lg2(S);
        sred[wid]     = (LN2f * A2 - sg * lnS) / S;   // kl_row (natural log)
        sred[8 + wid] = LN2f * E2;                    // Σ a*ln(a)
    }
    __syncthreads();
    if (wid == 0) {
        float kl = (lane < 8) ? sred[lane] : 0.f;
        float en = (lane < 8) ? sred[8 + lane] : 0.f;
        kl = warp_sum(kl);
        en = warp_sum(en);
        if (lane == 0) {
            atomicAdd(&g_acc[3], (double)kl);
            atomicAdd(&g_acc[4], (double)en);
        }
    }
}

// ---------------- finalize (and re-zero accumulators) ----------------
__global__ void final_kernel(const int* __restrict__ mel_len,
                             float* __restrict__ outp) {
    if (threadIdx.x == 0 && blockIdx.x == 0) {
        double nvalid = 0.0;
        for (int b = 0; b < Bc; b++) nvalid += (double)mel_len[b];
        nvalid *= (double)Mc;

        double loss_mel = (g_acc[0] + g_acc[1]) / nvalid;
        double loss_gate = g_acc[2] / (double)(Bc * Tc);
        double kl = g_acc[3] / (double)Bc / (double)Tc;
        if (kl > 150.0) kl = 150.0;
        double ent = -g_acc[4] / (double)(Bc * Tc);
        double ratio = ent / 3.5;
        if (ratio < 0.0) ratio = 0.0;
        double w;
        if (ent <= 3.5) {
            w = ratio > 0.2 ? ratio : 0.2;
        } else {
            w = 1.0;
        }
        double total = loss_mel + loss_gate + w * kl;
        outp[0] = (float)total;
        outp[1] = (float)loss_mel;
        outp[2] = (float)loss_gate;
        outp[3] = (float)kl;

        // reset for the next (replayed) invocation
        g_acc[0] = 0.0; g_acc[1] = 0.0; g_acc[2] = 0.0;
        g_acc[3] = 0.0; g_acc[4] = 0.0;
    }
}

extern "C" void kernel_launch(void* const* d_in, const int* in_sizes, int n_in,
                              void* d_out, int out_size) {
    const float* mel_out_postnet = (const float*)d_in[0];
    const float* mel_out         = (const float*)d_in[1];
    const float* gate_out        = (const float*)d_in[2];
    const float* alignments      = (const float*)d_in[3];
    const float* mel_target      = (const float*)d_in[4];
    const float* gate_target     = (const float*)d_in[5];
    const int*   mel_lengths     = (const int*)d_in[6];
    const int*   text_lengths    = (const int*)d_in[7];
    float* outp = (float*)d_out;

    mel_kernel<<<2368, 256>>>((const float4*)mel_out_postnet,
                              (const float4*)mel_out,
                              (const float4*)mel_target, mel_lengths);
    attn_gate_kernel<<<ATTN_BLOCKS + GATE_BLOCKS, 256>>>(
        (const float4*)alignments, text_lengths, gate_out, gate_target);
    final_kernel<<<1, 32>>>(mel_lengths, outp);
    (void)in_sizes; (void)n_in; (void)out_size;
}

// round 10
// speedup vs baseline: 1.4905x; 1.1200x over previous
#include <cuda_runtime.h>

#define Bc 64
#define Tc 2000
#define Lc 400
#define Mc 80
#define EPSc 1e-8f
#define LN2f 0.69314718055994531f
// sqrt(0.5 * log2(e)) — so that 2^{-((l-ep)*K2)^2} = e^{-z^2/2}, K2=SQHL2E/sigma
#define SQHL2E 0.84932180028801905f

// accumulators: 0=s1(mel1), 1=s2(mel2), 2=gate, 3=kl_sum, 4=ent_sum(Σ p*logp)
// Zero at module load; final_kernel re-zeros after use (graph-replay safe).
__device__ double g_acc[5];

__device__ __forceinline__ float fast_lg2(float x) {
    float r;
    asm("lg2.approx.f32 %0, %1;" : "=f"(r) : "f"(x));
    return r;
}
__device__ __forceinline__ float fast_ex2(float x) {
    float r;
    asm("ex2.approx.f32 %0, %1;" : "=f"(r) : "f"(x));
    return r;
}

__device__ __forceinline__ float warp_sum(float v) {
    v += __shfl_xor_sync(0xffffffffu, v, 16);
    v += __shfl_xor_sync(0xffffffffu, v, 8);
    v += __shfl_xor_sync(0xffffffffu, v, 4);
    v += __shfl_xor_sync(0xffffffffu, v, 2);
    v += __shfl_xor_sync(0xffffffffu, v, 1);
    return v;
}

// ---------------- mel L1 losses (2x unrolled grid-stride) ------------------
__global__ void __launch_bounds__(256)
mel_kernel(const float4* __restrict__ post,
           const float4* __restrict__ out,
           const float4* __restrict__ tgt,
           const int* __restrict__ mel_len) {
    const int n4 = Bc * Tc * Mc / 4;  // 2,048,000
    float s1 = 0.f, s2 = 0.f;
    int stride = gridDim.x * blockDim.x;
    for (int i = blockIdx.x * blockDim.x + threadIdx.x; i < n4; i += 2 * stride) {
        int i2 = i + stride;
        int row0 = i / (Mc / 4);
        int b0 = row0 / Tc;
        int t0 = row0 - b0 * Tc;
        bool v0 = t0 < __ldg(&mel_len[b0]);
        bool v1 = false;
        if (i2 < n4) {
            int row1 = i2 / (Mc / 4);
            int b1 = row1 / Tc;
            int t1 = row1 - b1 * Tc;
            v1 = t1 < __ldg(&mel_len[b1]);
        }
        if (v0) {
            float4 o = out[i], p = post[i], g = tgt[i];
            s1 += (fabsf(o.x - g.x) + fabsf(o.y - g.y)) + (fabsf(o.z - g.z) + fabsf(o.w - g.w));
            s2 += (fabsf(p.x - g.x) + fabsf(p.y - g.y)) + (fabsf(p.z - g.z) + fabsf(p.w - g.w));
        }
        if (v1) {
            float4 o = out[i2], p = post[i2], g = tgt[i2];
            s1 += (fabsf(o.x - g.x) + fabsf(o.y - g.y)) + (fabsf(o.z - g.z) + fabsf(o.w - g.w));
            s2 += (fabsf(p.x - g.x) + fabsf(p.y - g.y)) + (fabsf(p.z - g.z) + fabsf(p.w - g.w));
        }
    }
    __shared__ float sm1[8], sm2[8];
    int lane = threadIdx.x & 31, wid = threadIdx.x >> 5;
    s1 = warp_sum(s1);
    s2 = warp_sum(s2);
    if (lane == 0) { sm1[wid] = s1; sm2[wid] = s2; }
    __syncthreads();
    if (wid == 0) {
        float a = (lane < 8) ? sm1[lane] : 0.f;
        float b2 = (lane < 8) ? sm2[lane] : 0.f;
        a = warp_sum(a);
        b2 = warp_sum(b2);
        if (lane == 0) {
            atomicAdd(&g_acc[0], (double)a);
            atomicAdd(&g_acc[1], (double)b2);
        }
    }
}

// ---------------- attn: 4 rows per warp, 8 lanes per row -------------------
// Each 8-lane group owns one (b,t) row: 100 float4s in 13 group-iterations.
//   entropy (all elems):  E2 += a * lg2(a)
//   Gaussian (band-only, warp-uniform branch):
//     u=(l-ep)*K2, h=-u*u, g=ex2(h)=e^{-z^2/2}, mask l<Lb (exact int)
//   Row reduce: shfl_xor 1,2,4 within group (serves all 4 rows at once);
//   group leaders compute kl_row/ent_row; combine via shfl_xor 8,16.
#define ATTN_BLOCKS 4000
#define GATE_BLOCKS 64

__global__ void __launch_bounds__(256)
attn_gate_kernel(const float4* __restrict__ attn,
                 const int* __restrict__ text_len,
                 const float* __restrict__ gate_x,
                 const float* __restrict__ gate_z) {
    __shared__ float sred[16];
    int lane = threadIdx.x & 31, wid = threadIdx.x >> 5;

    if (blockIdx.x >= ATTN_BLOCKS) {
        // ---- gate BCE-with-logits ----
        int gid = blockIdx.x - ATTN_BLOCKS;
        const int n = Bc * Tc;
        int stride = GATE_BLOCKS * blockDim.x;
        float s = 0.f;
        for (int i = gid * blockDim.x + threadIdx.x; i < n; i += stride) {
            float xi = gate_x[i], zi = gate_z[i];
            s += fmaxf(xi, 0.f) - xi * zi + log1pf(__expf(-fabsf(xi)));
        }
        s = warp_sum(s);
        if (lane == 0) sred[wid] = s;
        __syncthreads();
        if (wid == 0) {
            float a = (lane < 8) ? sred[lane] : 0.f;
            a = warp_sum(a);
            if (lane == 0) atomicAdd(&g_acc[2], (double)a);
        }
        return;
    }

    int lig = lane & 7;           // lane in 8-lane group
    int grp = lane >> 3;          // group 0..3
    int rowid = (blockIdx.x * 8 + wid) * 4 + grp;   // [0, 128000)
    int b = (int)((unsigned)rowid / (unsigned)Tc);  // reciprocal-mul div
    int t = rowid - b * Tc;

    int Lb = __ldg(&text_len[b]);
    float sigma = fminf(fmaxf((float)Lb * 0.05f, 3.0f), 10.0f);
    int ep_i = (t * Lb) / Tc;
    if (ep_i > Lb - 1) ep_i = Lb - 1;
    float ep = (float)ep_i;
    float K2 = SQHL2E / sigma;
    int band_lo = ep_i - 67, band_hi = ep_i + 67;

    const float4* row = attn + rowid * (Lc / 4);

    float E2 = 0.f, sg = 0.f, A2 = 0.f;
#pragma unroll
    for (int it = 0; it < 13; it++) {
        int j = it * 8 + lig;
        bool jv = (it < 12) || (lig < 4);   // j < 100
        float4 a4 = jv ? row[j] : make_float4(1.f, 1.f, 1.f, 1.f);
        float a0 = fmaxf(a4.x, EPSc);
        float a1 = fmaxf(a4.y, EPSc);
        float a2 = fmaxf(a4.z, EPSc);
        float a3 = fmaxf(a4.w, EPSc);
        float p0 = fast_lg2(a0);
        float p1 = fast_lg2(a1);
        float p2 = fast_lg2(a2);
        float p3 = fast_lg2(a3);
        E2 += a0 * p0;
        E2 += a1 * p1;
        E2 += a2 * p2;
        E2 += a3 * p3;

        // this iteration covers l in [it*32, it*32+32) for every group
        int seg_lo = it * 32;
        bool inband = (seg_lo <= band_hi) && (seg_lo + 31 >= band_lo);
        if (__any_sync(0xffffffffu, inband)) {
            int l0 = j * 4;
            float u0 = ((float)l0 - ep) * K2;
            float u1 = u0 + K2;
            float u2 = u1 + K2;
            float u3 = u2 + K2;
            float h0 = -u0 * u0;
            float h1 = -u1 * u1;
            float h2 = -u2 * u2;
            float h3 = -u3 * u3;
            bool m = inband & jv;
            float g0 = (m && l0 + 0 < Lb) ? fast_ex2(h0) : 0.f;
            float g1 = (m && l0 + 1 < Lb) ? fast_ex2(h1) : 0.f;
            float g2 = (m && l0 + 2 < Lb) ? fast_ex2(h2) : 0.f;
            float g3 = (m && l0 + 3 < Lb) ? fast_ex2(h3) : 0.f;
            sg += (g0 + g1) + (g2 + g3);
            A2 += g0 * (h0 - p0);
            A2 += g1 * (h1 - p1);
            A2 += g2 * (h2 - p2);
            A2 += g3 * (h3 - p3);
        }
    }

    // ---- row reduction within each 8-lane group (3 steps, all 4 rows) ----
    sg += __shfl_xor_sync(0xffffffffu, sg, 1);
    sg += __shfl_xor_sync(0xffffffffu, sg, 2);
    sg += __shfl_xor_sync(0xffffffffu, sg, 4);
    A2 += __shfl_xor_sync(0xffffffffu, A2, 1);
    A2 += __shfl_xor_sync(0xffffffffu, A2, 2);
    A2 += __shfl_xor_sync(0xffffffffu, A2, 4);
    E2 += __shfl_xor_sync(0xffffffffu, E2, 1);
    E2 += __shfl_xor_sync(0xffffffffu, E2, 2);
    E2 += __shfl_xor_sync(0xffffffffu, E2, 4);

    // ---- group leaders: per-row nonlinear finalize ----
    float kl = 0.f, en = 0.f;
    if (lig == 0) {
        float S = sg + EPSc;
        float lnS = LN2f * fast_lg2(S);
        kl = (LN2f * A2 - sg * lnS) / S;
        en = LN2f * E2;
    }
    // combine the 4 group leaders (others hold 0)
    kl += __shfl_xor_sync(0xffffffffu, kl, 8);
    kl += __shfl_xor_sync(0xffffffffu, kl, 16);
    en += __shfl_xor_sync(0xffffffffu, en, 8);
    en += __shfl_xor_sync(0xffffffffu, en, 16);

    if (lane == 0) { sred[wid] = kl; sred[8 + wid] = en; }
    __syncthreads();
    if (wid == 0) {
        float k = (lane < 8) ? sred[lane] : 0.f;
        float e = (lane < 8) ? sred[8 + lane] : 0.f;
        k = warp_sum(k);
        e = warp_sum(e);
        if (lane == 0) {
            atomicAdd(&g_acc[3], (double)k);
            atomicAdd(&g_acc[4], (double)e);
        }
    }
}

// ---------------- finalize (and re-zero accumulators) ----------------
__global__ void final_kernel(const int* __restrict__ mel_len,
                             float* __restrict__ outp) {
    if (threadIdx.x == 0 && blockIdx.x == 0) {
        double nvalid = 0.0;
        for (int b = 0; b < Bc; b++) nvalid += (double)mel_len[b];
        nvalid *= (double)Mc;

        double loss_mel = (g_acc[0] + g_acc[1]) / nvalid;
        double loss_gate = g_acc[2] / (double)(Bc * Tc);
        double kl = g_acc[3] / (double)Bc / (double)Tc;
        if (kl > 150.0) kl = 150.0;
        double ent = -g_acc[4] / (double)(Bc * Tc);
        double ratio = ent / 3.5;
        if (ratio < 0.0) ratio = 0.0;
        double w;
        if (ent <= 3.5) {
            w = ratio > 0.2 ? ratio : 0.2;
        } else {
            w = 1.0;
        }
        double total = loss_mel + loss_gate + w * kl;
        outp[0] = (float)total;
        outp[1] = (float)loss_mel;
        outp[2] = (float)loss_gate;
        outp[3] = (float)kl;

        // reset for the next (replayed) invocation
        g_acc[0] = 0.0; g_acc[1] = 0.0; g_acc[2] = 0.0;
        g_acc[3] = 0.0; g_acc[4] = 0.0;
    }
}

extern "C" void kernel_launch(void* const* d_in, const int* in_sizes, int n_in,
                              void* d_out, int out_size) {
    const float* mel_out_postnet = (const float*)d_in[0];
    const float* mel_out         = (const float*)d_in[1];
    const float* gate_out        = (const float*)d_in[2];
    const float* alignments      = (const float*)d_in[3];
    const float* mel_target      = (const float*)d_in[4];
    const float* gate_target     = (const float*)d_in[5];
    const int*   mel_lengths     = (const int*)d_in[6];
    const int*   text_lengths    = (const int*)d_in[7];
    float* outp = (float*)d_out;

    mel_kernel<<<2368, 256>>>((const float4*)mel_out_postnet,
                              (const float4*)mel_out,
                              (const float4*)mel_target, mel_lengths);
    attn_gate_kernel<<<ATTN_BLOCKS + GATE_BLOCKS, 256>>>(
        (const float4*)alignments, text_lengths, gate_out, gate_target);
    final_kernel<<<1, 32>>>(mel_lengths, outp);
    (void)in_sizes; (void)n_in; (void)out_size;
}

// round 11
// speedup vs baseline: 1.7525x; 1.1758x over previous
#include <cuda_runtime.h>

#define Bc 64
#define Tc 2000
#define Lc 400
#define Mc 80
#define EPSc 1e-8f
#define LN2f 0.69314718055994531f
// sqrt(0.5 * log2(e)) — so that 2^{-((l-ep)*K2)^2} = e^{-z^2/2}, K2=SQHL2E/sigma
#define SQHL2E 0.84932180028801905f

// accumulators: 0=s1(mel1), 1=s2(mel2), 2=gate, 3=kl_sum, 4=ent_sum(Σ p*logp)
// Zero at module load; final_kernel re-zeros after use (graph-replay safe).
__device__ double g_acc[5];

__device__ __forceinline__ float fast_lg2(float x) {
    float r;
    asm("lg2.approx.f32 %0, %1;" : "=f"(r) : "f"(x));
    return r;
}
__device__ __forceinline__ float fast_ex2(float x) {
    float r;
    asm("ex2.approx.f32 %0, %1;" : "=f"(r) : "f"(x));
    return r;
}

__device__ __forceinline__ float warp_sum(float v) {
    v += __shfl_xor_sync(0xffffffffu, v, 16);
    v += __shfl_xor_sync(0xffffffffu, v, 8);
    v += __shfl_xor_sync(0xffffffffu, v, 4);
    v += __shfl_xor_sync(0xffffffffu, v, 2);
    v += __shfl_xor_sync(0xffffffffu, v, 1);
    return v;
}

// ---------------- attn: 4 rows per warp, 8 lanes per row, pipelined --------
__device__ __forceinline__ void attn_work(int aid, const float4* __restrict__ attn,
                                          const int* __restrict__ text_len,
                                          float* sred) {
    int lane = threadIdx.x & 31, wid = threadIdx.x >> 5;
    int lig = lane & 7;           // lane in 8-lane group
    int grp = lane >> 3;          // group 0..3
    int rowid = (aid * 8 + wid) * 4 + grp;          // [0, 128000)
    int b = (int)((unsigned)rowid / (unsigned)Tc);
    int t = rowid - b * Tc;

    int Lb = __ldg(&text_len[b]);
    float sigma = fminf(fmaxf((float)Lb * 0.05f, 3.0f), 10.0f);
    int ep_i = (t * Lb) / Tc;
    if (ep_i > Lb - 1) ep_i = Lb - 1;
    float ep = (float)ep_i;
    float K2 = SQHL2E / sigma;
    int band_lo = ep_i - 67, band_hi = ep_i + 67;

    const float4* row = attn + rowid * (Lc / 4);

    float E2 = 0.f, sg = 0.f, A2 = 0.f;
    float4 nxt = row[lig];                 // prefetch it=0
#pragma unroll
    for (int it = 0; it < 13; it++) {
        float4 a4 = nxt;
        if (it < 11) {
            nxt = row[(it + 1) * 8 + lig];
        } else if (it == 11) {
            nxt = (lig < 4) ? row[96 + lig] : make_float4(1.f, 1.f, 1.f, 1.f);
        }
        if (it == 12 && lig >= 4) a4 = make_float4(1.f, 1.f, 1.f, 1.f);

        float a0 = fmaxf(a4.x, EPSc);
        float a1 = fmaxf(a4.y, EPSc);
        float a2 = fmaxf(a4.z, EPSc);
        float a3 = fmaxf(a4.w, EPSc);
        float p0 = fast_lg2(a0);
        float p1 = fast_lg2(a1);
        float p2 = fast_lg2(a2);
        float p3 = fast_lg2(a3);
        E2 += a0 * p0;
        E2 += a1 * p1;
        E2 += a2 * p2;
        E2 += a3 * p3;

        int seg_lo = it * 32;              // l range of this iteration per group
        bool inband = (seg_lo <= band_hi) && (seg_lo + 31 >= band_lo);
        if (__any_sync(0xffffffffu, inband)) {
            int j = it * 8 + lig;
            int l0 = j * 4;
            bool jv = (it < 12) || (lig < 4);
            float u0 = ((float)l0 - ep) * K2;
            float u1 = u0 + K2;
            float u2 = u1 + K2;
            float u3 = u2 + K2;
            float h0 = -u0 * u0;
            float h1 = -u1 * u1;
            float h2 = -u2 * u2;
            float h3 = -u3 * u3;
            bool m = inband & jv;
            float g0 = (m && l0 + 0 < Lb) ? fast_ex2(h0) : 0.f;
            float g1 = (m && l0 + 1 < Lb) ? fast_ex2(h1) : 0.f;
            float g2 = (m && l0 + 2 < Lb) ? fast_ex2(h2) : 0.f;
            float g3 = (m && l0 + 3 < Lb) ? fast_ex2(h3) : 0.f;
            sg += (g0 + g1) + (g2 + g3);
            A2 += g0 * (h0 - p0);
            A2 += g1 * (h1 - p1);
            A2 += g2 * (h2 - p2);
            A2 += g3 * (h3 - p3);
        }
    }

    // row reduction within each 8-lane group (3 steps serve all 4 rows)
    sg += __shfl_xor_sync(0xffffffffu, sg, 1);
    sg += __shfl_xor_sync(0xffffffffu, sg, 2);
    sg += __shfl_xor_sync(0xffffffffu, sg, 4);
    A2 += __shfl_xor_sync(0xffffffffu, A2, 1);
    A2 += __shfl_xor_sync(0xffffffffu, A2, 2);
    A2 += __shfl_xor_sync(0xffffffffu, A2, 4);
    E2 += __shfl_xor_sync(0xffffffffu, E2, 1);
    E2 += __shfl_xor_sync(0xffffffffu, E2, 2);
    E2 += __shfl_xor_sync(0xffffffffu, E2, 4);

    float kl = 0.f, en = 0.f;
    if (lig == 0) {
        float S = sg + EPSc;
        float lnS = LN2f * fast_lg2(S);
        kl = (LN2f * A2 - sg * lnS) / S;
        en = LN2f * E2;
    }
    kl += __shfl_xor_sync(0xffffffffu, kl, 8);
    kl += __shfl_xor_sync(0xffffffffu, kl, 16);
    en += __shfl_xor_sync(0xffffffffu, en, 8);
    en += __shfl_xor_sync(0xffffffffu, en, 16);

    if (lane == 0) { sred[wid] = kl; sred[8 + wid] = en; }
    __syncthreads();
    if (wid == 0) {
        float k = (lane < 8) ? sred[lane] : 0.f;
        float e = (lane < 8) ? sred[8 + lane] : 0.f;
        k = warp_sum(k);
        e = warp_sum(e);
        if (lane == 0) {
            atomicAdd(&g_acc[3], (double)k);
            atomicAdd(&g_acc[4], (double)e);
        }
    }
}

// ---------------- mel L1 losses (4x unrolled grid-stride) ------------------
#define N_MEL 1200

__device__ __forceinline__ void mel_work(int mid,
                                         const float4* __restrict__ post,
                                         const float4* __restrict__ out,
                                         const float4* __restrict__ tgt,
                                         const int* __restrict__ mel_len,
                                         float* sred) {
    const int n4 = Bc * Tc * Mc / 4;  // 2,048,000
    const int stride = N_MEL * 256;
    float s1 = 0.f, s2 = 0.f;
    for (int i = mid * 256 + threadIdx.x; i < n4; i += 4 * stride) {
#pragma unroll
        for (int k = 0; k < 4; k++) {
            int idx = i + k * stride;
            if (idx < n4) {
                int rowi = idx / (Mc / 4);
                int b = rowi / Tc;
                int t = rowi - b * Tc;
                if (t < __ldg(&mel_len[b])) {
                    float4 o = out[idx], p = post[idx], g = tgt[idx];
                    s1 += (fabsf(o.x - g.x) + fabsf(o.y - g.y)) + (fabsf(o.z - g.z) + fabsf(o.w - g.w));
                    s2 += (fabsf(p.x - g.x) + fabsf(p.y - g.y)) + (fabsf(p.z - g.z) + fabsf(p.w - g.w));
                }
            }
        }
    }
    int lane = threadIdx.x & 31, wid = threadIdx.x >> 5;
    s1 = warp_sum(s1);
    s2 = warp_sum(s2);
    if (lane == 0) { sred[wid] = s1; sred[8 + wid] = s2; }
    __syncthreads();
    if (wid == 0) {
        float a = (lane < 8) ? sred[lane] : 0.f;
        float c = (lane < 8) ? sred[8 + lane] : 0.f;
        a = warp_sum(a);
        c = warp_sum(c);
        if (lane == 0) {
            atomicAdd(&g_acc[0], (double)a);
            atomicAdd(&g_acc[1], (double)c);
        }
    }
}

// ---------------- gate BCE-with-logits -------------------------------------
#define N_GATE 32

__device__ __forceinline__ void gate_work(int gid,
                                          const float* __restrict__ x,
                                          const float* __restrict__ z,
                                          float* sred) {
    const int n = Bc * Tc;
    int stride = N_GATE * 256;
    float s = 0.f;
    for (int i = gid * 256 + threadIdx.x; i < n; i += stride) {
        float xi = x[i], zi = z[i];
        s += fmaxf(xi, 0.f) - xi * zi + log1pf(__expf(-fabsf(xi)));
    }
    int lane = threadIdx.x & 31, wid = threadIdx.x >> 5;
    s = warp_sum(s);
    if (lane == 0) sred[wid] = s;
    __syncthreads();
    if (wid == 0) {
        float a = (lane < 8) ? sred[lane] : 0.f;
        a = warp_sum(a);
        if (lane == 0) atomicAdd(&g_acc[2], (double)a);
    }
}

// ---------------- fused kernel ---------------------------------------------
// bid < 5200:  q=bid/13, r=bid%13;  r<10 -> attn id q*10+r  ([0,4000))
//                                   r>=10 -> mel id q*3+(r-10) ([0,1200))
// bid >= 5200: gate block ([0,32))
#define ATTN_BLOCKS 4000
#define GRID_TOTAL (5200 + N_GATE)

__global__ void __launch_bounds__(256)
fused_kernel(const float4* __restrict__ post,
             const float4* __restrict__ out,
             const float*  __restrict__ gate_x,
             const float4* __restrict__ attn,
             const float4* __restrict__ tgt,
             const float*  __restrict__ gate_z,
             const int* __restrict__ mel_len,
             const int* __restrict__ text_len) {
    __shared__ float sred[16];
    int bid = blockIdx.x;
    if (bid >= 5200) {
        gate_work(bid - 5200, gate_x, gate_z, sred);
        return;
    }
    int q = bid / 13;
    int r = bid - 13 * q;
    if (r < 10) {
        attn_work(q * 10 + r, attn, text_len, sred);
    } else {
        mel_work(q * 3 + (r - 10), post, out, tgt, mel_len, sred);
    }
}

// ---------------- finalize (and re-zero accumulators) ----------------
__global__ void final_kernel(const int* __restrict__ mel_len,
                             float* __restrict__ outp) {
    if (threadIdx.x == 0 && blockIdx.x == 0) {
        double nvalid = 0.0;
        for (int b = 0; b < Bc; b++) nvalid += (double)mel_len[b];
        nvalid *= (double)Mc;

        double loss_mel = (g_acc[0] + g_acc[1]) / nvalid;
        double loss_gate = g_acc[2] / (double)(Bc * Tc);
        double kl = g_acc[3] / (double)Bc / (double)Tc;
        if (kl > 150.0) kl = 150.0;
        double ent = -g_acc[4] / (double)(Bc * Tc);
        double ratio = ent / 3.5;
        if (ratio < 0.0) ratio = 0.0;
        double w;
        if (ent <= 3.5) {
            w = ratio > 0.2 ? ratio : 0.2;
        } else {
            w = 1.0;
        }
        double total = loss_mel + loss_gate + w * kl;
        outp[0] = (float)total;
        outp[1] = (float)loss_mel;
        outp[2] = (float)loss_gate;
        outp[3] = (float)kl;

        // reset for the next (replayed) invocation
        g_acc[0] = 0.0; g_acc[1] = 0.0; g_acc[2] = 0.0;
        g_acc[3] = 0.0; g_acc[4] = 0.0;
    }
}

extern "C" void kernel_launch(void* const* d_in, const int* in_sizes, int n_in,
                              void* d_out, int out_size) {
    const float* mel_out_postnet = (const float*)d_in[0];
    const float* mel_out         = (const float*)d_in[1];
    const float* gate_out        = (const float*)d_in[2];
    const float* alignments      = (const float*)d_in[3];
    const float* mel_target      = (const float*)d_in[4];
    const float* gate_target     = (const float*)d_in[5];
    const int*   mel_lengths     = (const int*)d_in[6];
    const int*   text_lengths    = (const int*)d_in[7];
    float* outp = (float*)d_out;

    fused_kernel<<<GRID_TOTAL, 256>>>((const float4*)mel_out_postnet,
                                      (const float4*)mel_out,
                                      gate_out,
                                      (const float4*)alignments,
                                      (const float4*)mel_target,
                                      gate_target,
                                      mel_lengths, text_lengths);
    final_kernel<<<1, 32>>>(mel_lengths, outp);
    (void)in_sizes; (void)n_in; (void)out_size;
}